// round 15
// baseline (speedup 1.0000x reference)
#include <cuda_runtime.h>
#include <cuda_bf16.h>
#include <math.h>

#define FMA2(d,a,b) asm("fma.rn.f32x2 %0, %1, %2, %0;" : "+l"(d) : "l"(a), "l"(b))
#define DUP2(d,s)   asm("mov.b64 %0, {%1,%1};" : "=l"(d) : "f"(s))
#define PACK2(d,lo,hi) asm("mov.b64 %0, {%1,%2};" : "=l"(d) : "f"(lo), "f"(hi))

__device__ __forceinline__ float2 u2f(unsigned long long v) {
  float2 r; asm("mov.b64 {%0,%1}, %2;" : "=f"(r.x), "=f"(r.y) : "l"(v)); return r;
}

// ---------------- device scratch ----------------
__device__ float g_WT[2][300][1024];          // [dir][k][gate_row] transposed W_ih
__device__ float g_pre2[2][256][128][64][4];  // [dir][j][t][b][gate] 64MB
__device__ float g_hbuf[2][2][8][256][8];     // [parity][dir][bslice][j][bloc]
__device__ float g_hall[128][512][64];        // [t][c][b]
__device__ float g_parti[64*128*36];
__device__ float g_partj[64*128*36];
__device__ unsigned int g_cnt[16];            // [dir*8 + bslice]

__global__ void k_init_a() {
  if (threadIdx.x < 16) g_cnt[threadIdx.x] = 0u;
}
__global__ void k_init_b() {
  int i = blockIdx.x*blockDim.x + threadIdx.x;   // 65536 threads
  (&g_hbuf[0][0][0][0][0])[i] = 0.f;
}

// ============ 0) W transpose: g_WT[dir][k][row] = Wih[row][k] ============
__global__ void __launch_bounds__(256) k_trW(const float* __restrict__ Wf,
                                             const float* __restrict__ Wb)
{
  __shared__ float tile[64*61];
  int dir = blockIdx.z;
  int r0 = blockIdx.x*64;     // 16 blocks
  int k0 = blockIdx.y*60;     // 5 blocks
  const float* W = dir ? Wb : Wf;
  int tid = threadIdx.x;
  for (int e = tid; e < 3840; e += 256) {
    int r = e / 60, kk = e % 60;
    tile[r*61 + kk] = W[(size_t)(r0 + r)*300 + k0 + kk];
  }
  __syncthreads();
  for (int e = tid; e < 3840; e += 256) {
    int kk = e >> 6, r = e & 63;
    g_WT[dir][k0 + kk][r0 + r] = tile[r*61 + kk];
  }
}

// ============ 1) input GEMM v3: W slice SMEM-resident, 128 CTAs (one wave) ============
// grid (8 tg, 16 rt): dir = rt>>3, jt = rt&7. Each CTA: 16 timesteps, W loaded ONCE.
__global__ void __launch_bounds__(256,1) k_pre(
    const float* __restrict__ emb,
    const float* __restrict__ bihf, const float* __restrict__ bhhf,
    const float* __restrict__ bihb, const float* __restrict__ bhhb,
    const int* __restrict__ ids)
{
  extern __shared__ float sp[];
  float* W_full = sp;                 // [k][132] interleaved r=jl*4+gate: 300*132 floats
  float* A_s    = sp + 39600;         // [20][64]
  int*   id_s   = (int*)(sp + 39600 + 1280);

  int tid = threadIdx.x;
  int tg = blockIdx.x;                // 0..7
  int rt = blockIdx.y;                // 0..15
  int dir = rt >> 3, jt = rt & 7;

  // stage W slice once: 300 k x 128 rows (interleaved), via float4 from g_WT
  for (int e = tid; e < 9600; e += 256) {
    int k = e >> 5, rem = e & 31;
    int g = rem >> 3, q = rem & 7;
    float4 v = *(const float4*)&g_WT[dir][k][g*256 + jt*32 + q*4];
    W_full[k*132 + (q*4+0)*4 + g] = v.x;
    W_full[k*132 + (q*4+1)*4 + g] = v.y;
    W_full[k*132 + (q*4+2)*4 + g] = v.z;
    W_full[k*132 + (q*4+3)*4 + g] = v.w;
  }
  __syncthreads();

  int tokq = tid & 7, rowq = tid >> 3;      // rowq = jl (0..31)
  int tok0 = tokq*8;
  int j = jt*32 + rowq;
  float bias[4];
  #pragma unroll
  for (int g = 0; g < 4; g++) {
    int grow = g*256 + j;
    bias[g] = dir ? (bihb[grow] + bhhb[grow]) : (bihf[grow] + bhhf[grow]);
  }

  for (int ts = 0; ts < 16; ts++) {
    int t = tg*16 + ts;
    __syncthreads();
    if (tid < 64) id_s[tid] = ids[tid*128 + t];

    unsigned long long acc[4][4];
    #pragma unroll
    for (int i=0;i<4;i++){ acc[i][0]=0ull; acc[i][1]=0ull; acc[i][2]=0ull; acc[i][3]=0ull; }

    for (int kc = 0; kc < 15; kc++) {
      int k0 = kc*20;
      __syncthreads();
      for (int e = tid; e < 320; e += 256) {
        int d4 = e % 5, tok = e / 5;
        float4 v = *(const float4*)(emb + (size_t)id_s[tok]*300 + k0 + d4*4);
        A_s[(d4*4+0)*64 + tok] = v.x; A_s[(d4*4+1)*64 + tok] = v.y;
        A_s[(d4*4+2)*64 + tok] = v.z; A_s[(d4*4+3)*64 + tok] = v.w;
      }
      __syncthreads();
      #pragma unroll
      for (int k = 0; k < 20; k++) {
        int kk = k0 + k;
        float4 wv = *(const float4*)&W_full[kk*132 + rowq*4];
        ulonglong2 a0 = *(const ulonglong2*)&A_s[k*64 + tok0];
        ulonglong2 a1 = *(const ulonglong2*)&A_s[k*64 + tok0 + 4];
        unsigned long long w0d,w1d,w2d,w3d;
        DUP2(w0d, wv.x); DUP2(w1d, wv.y); DUP2(w2d, wv.z); DUP2(w3d, wv.w);
        FMA2(acc[0][0], w0d, a0.x); FMA2(acc[0][1], w0d, a0.y);
        FMA2(acc[0][2], w0d, a1.x); FMA2(acc[0][3], w0d, a1.y);
        FMA2(acc[1][0], w1d, a0.x); FMA2(acc[1][1], w1d, a0.y);
        FMA2(acc[1][2], w1d, a1.x); FMA2(acc[1][3], w1d, a1.y);
        FMA2(acc[2][0], w2d, a0.x); FMA2(acc[2][1], w2d, a0.y);
        FMA2(acc[2][2], w2d, a1.x); FMA2(acc[2][3], w2d, a1.y);
        FMA2(acc[3][0], w3d, a0.x); FMA2(acc[3][1], w3d, a0.y);
        FMA2(acc[3][2], w3d, a1.x); FMA2(acc[3][3], w3d, a1.y);
      }
    }
    // epilogue: acc[gate][tokpair] -> g_pre2[dir][j][t][tok][gate]
    float2 eg[4][4];
    #pragma unroll
    for (int g = 0; g < 4; g++)
      #pragma unroll
      for (int q = 0; q < 4; q++) eg[g][q] = u2f(acc[g][q]);
    float* outp = &g_pre2[dir][j][t][tok0][0];
    #pragma unroll
    for (int tt = 0; tt < 8; tt++) {
      int q = tt >> 1;
      float4 o;
      o.x = ((tt&1) ? eg[0][q].y : eg[0][q].x) + bias[0];
      o.y = ((tt&1) ? eg[1][q].y : eg[1][q].x) + bias[1];
      o.z = ((tt&1) ? eg[2][q].y : eg[2][q].x) + bias[2];
      o.w = ((tt&1) ? eg[3][q].y : eg[3][q].x) + bias[3];
      *(float4*)(outp + tt*4) = o;
    }
  }
}

// ============ 2) persistent BiLSTM (R13 verbatim — best measured: 518us) ============
__global__ void __launch_bounds__(256,1) k_lstm(const float* __restrict__ Whhf,
                                                const float* __restrict__ Whhb)
{
  extern __shared__ float sm[];
  float* W_s    = sm;            // [k*132 + r], 33792 floats
  float* h_s    = sm + 33792;    // [k][bloc] 256x8, 2048 floats
  float* part_s = sm + 35840;    // [kc*1024 + r*8 + bl], 4096 floats

  int tid = threadIdx.x, cta = blockIdx.x;
  int dir = cta >> 6, rem = cta & 63;
  int bslice = rem >> 3, rslice = rem & 7;
  const float* Whh = dir ? Whhb : Whhf;

  for (int e = tid; e < 32768; e += 256) {
    int r = e >> 8, k = e & 255;
    int grow = (r >> 5)*256 + rslice*32 + (r & 31);
    W_s[k*132 + r] = Whh[(size_t)grow*256 + k];
  }
  __syncthreads();

  int w8 = tid >> 5, lane = tid & 31;
  int kc = w8 & 3, rw = w8 >> 2;
  int rbase = rw*64 + (lane >> 1)*4;
  int bbase = (lane & 1)*4;
  int kstart = kc*64;
  int jloc = tid >> 3, bloc = tid & 7;
  int j = rslice*32 + jloc;
  int gb = bslice*8 + bloc;
  const float4* pgp = (const float4*)&g_pre2[dir][j][0][0][0];
  unsigned cidx = (unsigned)(dir*8 + bslice);
  unsigned hs_u32 = (unsigned)__cvta_generic_to_shared(h_s);
  float c = 0.f;

  for (int sidx = 0; sidx < 128; sidx++) {
    int t = dir ? (127 - sidx) : sidx;
    float4 pg = __ldg(&pgp[t*64 + gb]);

    if (sidx > 0) {
      if (tid == 0) {
        unsigned tgt = (unsigned)(sidx*8);
        while (*((volatile unsigned int*)&g_cnt[cidx]) < tgt) { }
        __threadfence();
      }
      __syncthreads();
    }
    {
      const float4* src = (const float4*)&g_hbuf[sidx & 1][dir][bslice][0][0];
      asm volatile("cp.async.cg.shared.global [%0], [%1], 16;"
                   :: "r"(hs_u32 + tid*16), "l"(src + tid));
      asm volatile("cp.async.cg.shared.global [%0], [%1], 16;"
                   :: "r"(hs_u32 + (tid+256)*16), "l"(src + tid + 256));
      asm volatile("cp.async.commit_group;");
      asm volatile("cp.async.wait_group 0;" ::: "memory");
    }
    __syncthreads();

    unsigned long long a00=0,a01=0,a10=0,a11=0,a20=0,a21=0,a30=0,a31=0;
    #pragma unroll 4
    for (int kk = 0; kk < 64; kk++) {
      int k = kstart + kk;
      float4 wv = *(const float4*)&W_s[k*132 + rbase];
      ulonglong2 hv = *(const ulonglong2*)&h_s[k*8 + bbase];
      unsigned long long w0d,w1d,w2d,w3d;
      DUP2(w0d, wv.x); DUP2(w1d, wv.y); DUP2(w2d, wv.z); DUP2(w3d, wv.w);
      FMA2(a00, w0d, hv.x); FMA2(a01, w0d, hv.y);
      FMA2(a10, w1d, hv.x); FMA2(a11, w1d, hv.y);
      FMA2(a20, w2d, hv.x); FMA2(a21, w2d, hv.y);
      FMA2(a30, w3d, hv.x); FMA2(a31, w3d, hv.y);
    }
    {
      ulonglong2 v;
      v.x = a00; v.y = a01; *(ulonglong2*)&part_s[kc*1024 + (rbase+0)*8 + bbase] = v;
      v.x = a10; v.y = a11; *(ulonglong2*)&part_s[kc*1024 + (rbase+1)*8 + bbase] = v;
      v.x = a20; v.y = a21; *(ulonglong2*)&part_s[kc*1024 + (rbase+2)*8 + bbase] = v;
      v.x = a30; v.y = a31; *(ulonglong2*)&part_s[kc*1024 + (rbase+3)*8 + bbase] = v;
    }
    __syncthreads();

    int ri = jloc, rf = 32 + jloc, rg = 64 + jloc, ro = 96 + jloc;
    float iv = pg.x + part_s[ri*8+bloc] + part_s[1024 + ri*8+bloc]
                    + part_s[2048 + ri*8+bloc] + part_s[3072 + ri*8+bloc];
    float fv = pg.y + part_s[rf*8+bloc] + part_s[1024 + rf*8+bloc]
                    + part_s[2048 + rf*8+bloc] + part_s[3072 + rf*8+bloc];
    float gv = pg.z + part_s[rg*8+bloc] + part_s[1024 + rg*8+bloc]
                    + part_s[2048 + rg*8+bloc] + part_s[3072 + rg*8+bloc];
    float ov = pg.w + part_s[ro*8+bloc] + part_s[1024 + ro*8+bloc]
                    + part_s[2048 + ro*8+bloc] + part_s[3072 + ro*8+bloc];
    iv = 1.f/(1.f+__expf(-iv));
    fv = 1.f/(1.f+__expf(-fv));
    gv = tanhf(gv);
    ov = 1.f/(1.f+__expf(-ov));
    c = fv*c + iv*gv;
    float h = ov*tanhf(c);
    g_hbuf[(sidx+1)&1][dir][bslice][j][bloc] = h;
    g_hall[t][dir*256 + j][gb] = h;
    __syncthreads();
    if (tid == 0) { __threadfence(); atomicAdd(&g_cnt[cidx], 1u); }
  }
}

// ============ 3a) combined GEMM, conflict-free h layout [k][b] ============
__global__ void __launch_bounds__(256) k_evcomb(const float* __restrict__ Wev,
                                                const float* __restrict__ bev,
                                                const float* __restrict__ Warg,
                                                float* __restrict__ out0)
{
  __shared__ __align__(16) float W_s[106*64];
  __shared__ __align__(16) float h_s[64*64];
  int t = blockIdx.x;
  int tid = threadIdx.x;
  int b = tid & 63;
  int g = tid >> 6;
  unsigned long long acc2[27];
  #pragma unroll
  for (int i=0;i<27;i++) acc2[i] = 0ull;

  for (int c0 = 0; c0 < 512; c0 += 64) {
    __syncthreads();
    for (int e = tid; e < 106*64; e += 256) {
      int r = e >> 6, kk = e & 63;
      float w;
      if (r < 34)       w = Wev[(size_t)r*545 + c0 + kk];
      else if (r < 70)  w = Warg[(size_t)(r-34)*1024 + c0 + kk];
      else              w = Warg[(size_t)(r-70)*1024 + 512 + c0 + kk];
      W_s[e] = w;
    }
    for (int e = tid; e < 4096; e += 256) {
      int kk = e >> 6, bb = e & 63;
      h_s[kk*64 + bb] = g_hall[t][c0+kk][bb];   // [k][b]: coalesced both sides
    }
    __syncthreads();
    #pragma unroll 4
    for (int k = 0; k < 64; k += 4) {
      float h0 = h_s[(k+0)*64 + b];
      float h1 = h_s[(k+1)*64 + b];
      float h2 = h_s[(k+2)*64 + b];
      float h3 = h_s[(k+3)*64 + b];
      unsigned long long hx, hy;
      PACK2(hx, h0, h1); PACK2(hy, h2, h3);
      #pragma unroll
      for (int ii = 0; ii < 27; ii++) {
        int r = g + ii*4;
        if (r < 106) {
          ulonglong2 wv = *(const ulonglong2*)&W_s[r*64 + k];
          FMA2(acc2[ii], wv.x, hx);
          FMA2(acc2[ii], wv.y, hy);
        }
      }
    }
  }
  #pragma unroll
  for (int ii = 0; ii < 27; ii++) {
    int r = g + ii*4;
    if (r < 106) {
      float2 f = u2f(acc2[ii]);
      float v = f.x + f.y;
      if (r < 34)
        out0[((size_t)b*128 + t)*34 + r] = v + bev[r];
      else if (r < 70)
        g_partj[((size_t)b*128 + t)*36 + (r-34)] = v;
      else
        g_parti[((size_t)b*128 + t)*36 + (r-70)] = v;
    }
  }
}

// ============ 3b) event scan: SMEM-resident (R14 version, passed) ============
__global__ void __launch_bounds__(32) k_evscan(const float* __restrict__ Wev,
                                               float* __restrict__ out0)
{
  __shared__ float base[128*34];
  int b = blockIdx.x;
  int lane = threadIdx.x;
  float* basep = out0 + (size_t)b*128*34;
  for (int e = lane; e < 4352; e += 32) base[e] = basep[e];
  __syncwarp();

  float add0 = 0.f, add1 = 0.f;
  unsigned long long gmask = 0ull;
  for (int t = 0; t < 128; t++) {
    float v0 = base[t*34 + lane] + add0;
    float v1 = (lane < 2) ? (base[t*34 + 32 + lane] + add1) : -INFINITY;
    base[t*34 + lane] = v0;
    if (lane < 2) base[t*34 + 32 + lane] = v1;

    float mv = v0; int mi = lane;
    if (lane < 2 && v1 > mv) { mv = v1; mi = lane + 32; }
    #pragma unroll
    for (int o = 16; o > 0; o >>= 1) {
      float ov = __shfl_xor_sync(0xffffffffu, mv, o);
      int   oi = __shfl_xor_sync(0xffffffffu, mi, o);
      if (ov > mv || (ov == mv && oi < mi)) { mv = ov; mi = oi; }
    }
    if (mi > 0) {
      unsigned long long bit = 1ull << (mi - 1);
      if (!(gmask & bit)) {
        gmask |= bit;
        add0 += Wev[(size_t)lane*545 + 512 + (mi-1)];
        if (lane < 2) add1 += Wev[(size_t)(lane+32)*545 + 512 + (mi-1)];
      }
    }
  }
  __syncwarp();
  for (int e = lane; e < 4352; e += 32) basep[e] = base[e];
}

// ============ 5) broadcast add (unchanged) ============
__global__ void __launch_bounds__(256) k_add(const float* __restrict__ barg,
                                             float* __restrict__ out1)
{
  __shared__ __align__(16) float pjb[128*36];
  int b = blockIdx.x >> 1, half = blockIdx.x & 1;
  int tid = threadIdx.x;
  for (int e = tid; e < 4608; e += 256)
    pjb[e] = g_partj[(size_t)b*4608 + e] + barg[e % 36];
  __syncthreads();
  const float4* pjb4 = (const float4*)pjb;
  float* outb = out1 + (size_t)b*589824 + (size_t)half*294912;
  const float* pib = &g_parti[(size_t)b*4608 + (size_t)half*64*36];
  for (int i = 0; i < 64; i++) {
    const float* pi = pib + i*36;
    float4* od = (float4*)(outb + (size_t)i*4608);
    int a0 = (tid*4) % 36;
    for (int f = tid; f < 1152; f += 256) {
      float4 v = pjb4[f];
      int aa = a0;
      v.x += __ldg(&pi[aa]); aa = (aa==35)?0:aa+1;
      v.y += __ldg(&pi[aa]); aa = (aa==35)?0:aa+1;
      v.z += __ldg(&pi[aa]); aa = (aa==35)?0:aa+1;
      v.w += __ldg(&pi[aa]);
      od[f] = v;
      a0 += 16;
      if (a0 >= 36) a0 -= 36;
    }
  }
}

extern "C" void kernel_launch(void* const* d_in, const int* in_sizes, int n_in,
                              void* d_out, int out_size) {
  const float* emb  = (const float*)d_in[0];
  const float* Wihf = (const float*)d_in[1];
  const float* Whhf = (const float*)d_in[2];
  const float* bihf = (const float*)d_in[3];
  const float* bhhf = (const float*)d_in[4];
  const float* Wihb = (const float*)d_in[5];
  const float* Whhb = (const float*)d_in[6];
  const float* bihb = (const float*)d_in[7];
  const float* bhhb = (const float*)d_in[8];
  const float* Wev  = (const float*)d_in[9];
  const float* bev  = (const float*)d_in[10];
  const float* Warg = (const float*)d_in[11];
  const float* barg = (const float*)d_in[12];
  const int*   ids  = (const int*)d_in[13];
  float* out = (float*)d_out;

  cudaFuncSetAttribute(k_lstm, cudaFuncAttributeMaxDynamicSharedMemorySize, 159744);
  cudaFuncSetAttribute(k_pre,  cudaFuncAttributeMaxDynamicSharedMemorySize, 164096);

  k_init_a<<<1, 32>>>();                                            // 1
  k_init_b<<<256, 256>>>();                                         // 2
  dim3 gt(16, 5, 2);
  k_trW<<<gt, 256>>>(Wihf, Wihb);                                   // 3
  dim3 gp(8, 16);
  k_pre<<<gp, 256, 164096>>>(emb, bihf, bhhf, bihb, bhhb, ids);     // 4 (profiled slot)
  k_lstm<<<128, 256, 159744>>>(Whhf, Whhb);                         // 5
  k_evcomb<<<128, 256>>>(Wev, bev, Warg, out);                      // 6
  k_evscan<<<64, 32>>>(Wev, out);                                   // 7
  k_add<<<128, 256>>>(barg, out + 278528);                          // 8
}

// round 16
// speedup vs baseline: 1.0969x; 1.0969x over previous
#include <cuda_runtime.h>
#include <cuda_bf16.h>
#include <math.h>

#define FMA2(d,a,b) asm("fma.rn.f32x2 %0, %1, %2, %0;" : "+l"(d) : "l"(a), "l"(b))
#define DUP2(d,s)   asm("mov.b64 %0, {%1,%1};" : "=l"(d) : "f"(s))
#define PACK2(d,lo,hi) asm("mov.b64 %0, {%1,%2};" : "=l"(d) : "f"(lo), "f"(hi))

__device__ __forceinline__ float2 u2f(unsigned long long v) {
  float2 r; asm("mov.b64 {%0,%1}, %2;" : "=f"(r.x), "=f"(r.y) : "l"(v)); return r;
}

// ---------------- device scratch ----------------
__device__ float g_pre2[2][256][128][64][4];  // [dir][j][t][b][gate] 64MB
__device__ float g_hbuf[2][2][8][256][8];     // [parity][dir][bslice][j][bloc]
__device__ float g_hall[128][512][64];        // [t][c][b]
__device__ float g_parti[64*128*36];
__device__ float g_partj[64*128*36];
__device__ unsigned int g_cnt[16];            // [dir*8 + bslice]

__global__ void k_init_a() {
  if (threadIdx.x < 16) g_cnt[threadIdx.x] = 0u;
}
__global__ void k_init_b() {
  int i = blockIdx.x*blockDim.x + threadIdx.x;   // 65536 threads
  (&g_hbuf[0][0][0][0][0])[i] = 0.f;
}

// ============ 1) input GEMM (R13 verbatim): gate-interleaved, coalesced staging ======
__global__ void __launch_bounds__(256) k_pre(
    const float* __restrict__ emb, const float* __restrict__ Wf, const float* __restrict__ Wb,
    const float* __restrict__ bihf, const float* __restrict__ bhhf,
    const float* __restrict__ bihb, const float* __restrict__ bhhb,
    const int* __restrict__ ids)
{
  __shared__ __align__(16) float  A_s[20][64];
  __shared__ __align__(16) float2 W2p[20*128];
  __shared__ int id_s[64];
  int tid = threadIdx.x;
  int t  = blockIdx.x;
  int rt = blockIdx.y;
  int dir = rt >> 3, jt = rt & 7;
  if (tid < 64) id_s[tid] = ids[tid*128 + t];   // b = tid
  __syncthreads();

  const float* Wih = dir ? Wb : Wf;
  int tokq = tid & 7, rowq = tid >> 3;          // rowq = j_local (0..31)
  int tok0 = tokq*8;
  int j = jt*32 + rowq;
  unsigned long long acc[4][4];                 // [gate][token-pair]
  #pragma unroll
  for (int i=0;i<4;i++){ acc[i][0]=0ull; acc[i][1]=0ull; acc[i][2]=0ull; acc[i][3]=0ull; }

  for (int kc = 0; kc < 15; kc++) {
    int k0 = kc*20;
    __syncthreads();
    for (int e = tid; e < 320; e += 256) {
      int d4 = e % 5, tok = e / 5;
      float4 v = *(const float4*)(emb + (size_t)id_s[tok]*300 + k0 + d4*4);
      A_s[d4*4+0][tok] = v.x; A_s[d4*4+1][tok] = v.y;
      A_s[d4*4+2][tok] = v.z; A_s[d4*4+3][tok] = v.w;
    }
    // coalesced staging: consecutive lanes -> consecutive r -> contiguous STS.64
    for (int e = tid; e < 2560; e += 256) {
      int k = e >> 7, r = e & 127;              // r = jl*4 + gate
      int gate = r & 3, jl = r >> 2;
      int wrow = gate*256 + jt*32 + jl;
      float w = Wih[(size_t)wrow*300 + k0 + k];
      W2p[k*128 + r] = make_float2(w, w);
    }
    __syncthreads();
    #pragma unroll
    for (int k = 0; k < 20; k++) {
      ulonglong2 a0 = *(const ulonglong2*)&A_s[k][tok0];
      ulonglong2 a1 = *(const ulonglong2*)&A_s[k][tok0+4];
      ulonglong2 wA = *(const ulonglong2*)&W2p[k*128 + rowq*4];
      ulonglong2 wB = *(const ulonglong2*)&W2p[k*128 + rowq*4 + 2];
      FMA2(acc[0][0], wA.x, a0.x); FMA2(acc[0][1], wA.x, a0.y);
      FMA2(acc[0][2], wA.x, a1.x); FMA2(acc[0][3], wA.x, a1.y);
      FMA2(acc[1][0], wA.y, a0.x); FMA2(acc[1][1], wA.y, a0.y);
      FMA2(acc[1][2], wA.y, a1.x); FMA2(acc[1][3], wA.y, a1.y);
      FMA2(acc[2][0], wB.x, a0.x); FMA2(acc[2][1], wB.x, a0.y);
      FMA2(acc[2][2], wB.x, a1.x); FMA2(acc[2][3], wB.x, a1.y);
      FMA2(acc[3][0], wB.y, a0.x); FMA2(acc[3][1], wB.y, a0.y);
      FMA2(acc[3][2], wB.y, a1.x); FMA2(acc[3][3], wB.y, a1.y);
    }
  }
  float2 eg[4][4];
  float bias[4];
  #pragma unroll
  for (int g = 0; g < 4; g++) {
    int grow = g*256 + j;
    bias[g] = dir ? (bihb[grow] + bhhb[grow]) : (bihf[grow] + bhhf[grow]);
    #pragma unroll
    for (int q = 0; q < 4; q++) eg[g][q] = u2f(acc[g][q]);
  }
  float* outp = &g_pre2[dir][j][t][tok0][0];
  #pragma unroll
  for (int tt = 0; tt < 8; tt++) {
    int q = tt >> 1;
    float4 o;
    o.x = ((tt&1) ? eg[0][q].y : eg[0][q].x) + bias[0];
    o.y = ((tt&1) ? eg[1][q].y : eg[1][q].x) + bias[1];
    o.z = ((tt&1) ? eg[2][q].y : eg[2][q].x) + bias[2];
    o.w = ((tt&1) ? eg[3][q].y : eg[3][q].x) + bias[3];
    *(float4*)(outp + tt*4) = o;
  }
}

// ============ 2) persistent BiLSTM (R13 verbatim — best measured: 518us) ============
__global__ void __launch_bounds__(256,1) k_lstm(const float* __restrict__ Whhf,
                                                const float* __restrict__ Whhb)
{
  extern __shared__ float sm[];
  float* W_s    = sm;            // [k*132 + r], 33792 floats
  float* h_s    = sm + 33792;    // [k][bloc] 256x8, 2048 floats
  float* part_s = sm + 35840;    // [kc*1024 + r*8 + bl], 4096 floats

  int tid = threadIdx.x, cta = blockIdx.x;
  int dir = cta >> 6, rem = cta & 63;
  int bslice = rem >> 3, rslice = rem & 7;
  const float* Whh = dir ? Whhb : Whhf;

  for (int e = tid; e < 32768; e += 256) {
    int r = e >> 8, k = e & 255;
    int grow = (r >> 5)*256 + rslice*32 + (r & 31);
    W_s[k*132 + r] = Whh[(size_t)grow*256 + k];
  }
  __syncthreads();

  int w8 = tid >> 5, lane = tid & 31;
  int kc = w8 & 3, rw = w8 >> 2;
  int rbase = rw*64 + (lane >> 1)*4;
  int bbase = (lane & 1)*4;
  int kstart = kc*64;
  int jloc = tid >> 3, bloc = tid & 7;
  int j = rslice*32 + jloc;
  int gb = bslice*8 + bloc;
  const float4* pgp = (const float4*)&g_pre2[dir][j][0][0][0];
  unsigned cidx = (unsigned)(dir*8 + bslice);
  unsigned hs_u32 = (unsigned)__cvta_generic_to_shared(h_s);
  float c = 0.f;

  for (int sidx = 0; sidx < 128; sidx++) {
    int t = dir ? (127 - sidx) : sidx;
    float4 pg = __ldg(&pgp[t*64 + gb]);

    if (sidx > 0) {
      if (tid == 0) {
        unsigned tgt = (unsigned)(sidx*8);
        while (*((volatile unsigned int*)&g_cnt[cidx]) < tgt) { }
        __threadfence();
      }
      __syncthreads();
    }
    {
      const float4* src = (const float4*)&g_hbuf[sidx & 1][dir][bslice][0][0];
      asm volatile("cp.async.cg.shared.global [%0], [%1], 16;"
                   :: "r"(hs_u32 + tid*16), "l"(src + tid));
      asm volatile("cp.async.cg.shared.global [%0], [%1], 16;"
                   :: "r"(hs_u32 + (tid+256)*16), "l"(src + tid + 256));
      asm volatile("cp.async.commit_group;");
      asm volatile("cp.async.wait_group 0;" ::: "memory");
    }
    __syncthreads();

    unsigned long long a00=0,a01=0,a10=0,a11=0,a20=0,a21=0,a30=0,a31=0;
    #pragma unroll 4
    for (int kk = 0; kk < 64; kk++) {
      int k = kstart + kk;
      float4 wv = *(const float4*)&W_s[k*132 + rbase];
      ulonglong2 hv = *(const ulonglong2*)&h_s[k*8 + bbase];
      unsigned long long w0d,w1d,w2d,w3d;
      DUP2(w0d, wv.x); DUP2(w1d, wv.y); DUP2(w2d, wv.z); DUP2(w3d, wv.w);
      FMA2(a00, w0d, hv.x); FMA2(a01, w0d, hv.y);
      FMA2(a10, w1d, hv.x); FMA2(a11, w1d, hv.y);
      FMA2(a20, w2d, hv.x); FMA2(a21, w2d, hv.y);
      FMA2(a30, w3d, hv.x); FMA2(a31, w3d, hv.y);
    }
    {
      ulonglong2 v;
      v.x = a00; v.y = a01; *(ulonglong2*)&part_s[kc*1024 + (rbase+0)*8 + bbase] = v;
      v.x = a10; v.y = a11; *(ulonglong2*)&part_s[kc*1024 + (rbase+1)*8 + bbase] = v;
      v.x = a20; v.y = a21; *(ulonglong2*)&part_s[kc*1024 + (rbase+2)*8 + bbase] = v;
      v.x = a30; v.y = a31; *(ulonglong2*)&part_s[kc*1024 + (rbase+3)*8 + bbase] = v;
    }
    __syncthreads();

    int ri = jloc, rf = 32 + jloc, rg = 64 + jloc, ro = 96 + jloc;
    float iv = pg.x + part_s[ri*8+bloc] + part_s[1024 + ri*8+bloc]
                    + part_s[2048 + ri*8+bloc] + part_s[3072 + ri*8+bloc];
    float fv = pg.y + part_s[rf*8+bloc] + part_s[1024 + rf*8+bloc]
                    + part_s[2048 + rf*8+bloc] + part_s[3072 + rf*8+bloc];
    float gv = pg.z + part_s[rg*8+bloc] + part_s[1024 + rg*8+bloc]
                    + part_s[2048 + rg*8+bloc] + part_s[3072 + rg*8+bloc];
    float ov = pg.w + part_s[ro*8+bloc] + part_s[1024 + ro*8+bloc]
                    + part_s[2048 + ro*8+bloc] + part_s[3072 + ro*8+bloc];
    iv = 1.f/(1.f+__expf(-iv));
    fv = 1.f/(1.f+__expf(-fv));
    gv = tanhf(gv);
    ov = 1.f/(1.f+__expf(-ov));
    c = fv*c + iv*gv;
    float h = ov*tanhf(c);
    g_hbuf[(sidx+1)&1][dir][bslice][j][bloc] = h;
    g_hall[t][dir*256 + j][gb] = h;
    __syncthreads();
    if (tid == 0) { __threadfence(); atomicAdd(&g_cnt[cidx], 1u); }
  }
}

// ============ 3a) combined GEMM, conflict-free h layout [k][b] (R15, passed) ============
__global__ void __launch_bounds__(256) k_evcomb(const float* __restrict__ Wev,
                                                const float* __restrict__ bev,
                                                const float* __restrict__ Warg,
                                                float* __restrict__ out0)
{
  __shared__ __align__(16) float W_s[106*64];
  __shared__ __align__(16) float h_s[64*64];
  int t = blockIdx.x;
  int tid = threadIdx.x;
  int b = tid & 63;
  int g = tid >> 6;
  unsigned long long acc2[27];
  #pragma unroll
  for (int i=0;i<27;i++) acc2[i] = 0ull;

  for (int c0 = 0; c0 < 512; c0 += 64) {
    __syncthreads();
    for (int e = tid; e < 106*64; e += 256) {
      int r = e >> 6, kk = e & 63;
      float w;
      if (r < 34)       w = Wev[(size_t)r*545 + c0 + kk];
      else if (r < 70)  w = Warg[(size_t)(r-34)*1024 + c0 + kk];
      else              w = Warg[(size_t)(r-70)*1024 + 512 + c0 + kk];
      W_s[e] = w;
    }
    for (int e = tid; e < 4096; e += 256) {
      int kk = e >> 6, bb = e & 63;
      h_s[kk*64 + bb] = g_hall[t][c0+kk][bb];   // [k][b]: coalesced both sides
    }
    __syncthreads();
    #pragma unroll 4
    for (int k = 0; k < 64; k += 4) {
      float h0 = h_s[(k+0)*64 + b];
      float h1 = h_s[(k+1)*64 + b];
      float h2 = h_s[(k+2)*64 + b];
      float h3 = h_s[(k+3)*64 + b];
      unsigned long long hx, hy;
      PACK2(hx, h0, h1); PACK2(hy, h2, h3);
      #pragma unroll
      for (int ii = 0; ii < 27; ii++) {
        int r = g + ii*4;
        if (r < 106) {
          ulonglong2 wv = *(const ulonglong2*)&W_s[r*64 + k];
          FMA2(acc2[ii], wv.x, hx);
          FMA2(acc2[ii], wv.y, hy);
        }
      }
    }
  }
  #pragma unroll
  for (int ii = 0; ii < 27; ii++) {
    int r = g + ii*4;
    if (r < 106) {
      float2 f = u2f(acc2[ii]);
      float v = f.x + f.y;
      if (r < 34)
        out0[((size_t)b*128 + t)*34 + r] = v + bev[r];
      else if (r < 70)
        g_partj[((size_t)b*128 + t)*36 + (r-34)] = v;
      else
        g_parti[((size_t)b*128 + t)*36 + (r-70)] = v;
    }
  }
}

// ============ 3b) event scan: SMEM-resident (R15, passed) ============
__global__ void __launch_bounds__(32) k_evscan(const float* __restrict__ Wev,
                                               float* __restrict__ out0)
{
  __shared__ float base[128*34];
  int b = blockIdx.x;
  int lane = threadIdx.x;
  float* basep = out0 + (size_t)b*128*34;
  for (int e = lane; e < 4352; e += 32) base[e] = basep[e];
  __syncwarp();

  float add0 = 0.f, add1 = 0.f;
  unsigned long long gmask = 0ull;
  for (int t = 0; t < 128; t++) {
    float v0 = base[t*34 + lane] + add0;
    float v1 = (lane < 2) ? (base[t*34 + 32 + lane] + add1) : -INFINITY;
    base[t*34 + lane] = v0;
    if (lane < 2) base[t*34 + 32 + lane] = v1;

    float mv = v0; int mi = lane;
    if (lane < 2 && v1 > mv) { mv = v1; mi = lane + 32; }
    #pragma unroll
    for (int o = 16; o > 0; o >>= 1) {
      float ov = __shfl_xor_sync(0xffffffffu, mv, o);
      int   oi = __shfl_xor_sync(0xffffffffu, mi, o);
      if (ov > mv || (ov == mv && oi < mi)) { mv = ov; mi = oi; }
    }
    if (mi > 0) {
      unsigned long long bit = 1ull << (mi - 1);
      if (!(gmask & bit)) {
        gmask |= bit;
        add0 += Wev[(size_t)lane*545 + 512 + (mi-1)];
        if (lane < 2) add1 += Wev[(size_t)(lane+32)*545 + 512 + (mi-1)];
      }
    }
  }
  __syncwarp();
  for (int e = lane; e < 4352; e += 32) basep[e] = base[e];
}

// ============ 5) broadcast add (R13 verbatim) ============
__global__ void __launch_bounds__(256) k_add(const float* __restrict__ barg,
                                             float* __restrict__ out1)
{
  __shared__ __align__(16) float pjb[128*36];
  int b = blockIdx.x >> 1, half = blockIdx.x & 1;
  int tid = threadIdx.x;
  for (int e = tid; e < 4608; e += 256)
    pjb[e] = g_partj[(size_t)b*4608 + e] + barg[e % 36];
  __syncthreads();
  const float4* pjb4 = (const float4*)pjb;
  float* outb = out1 + (size_t)b*589824 + (size_t)half*294912;
  const float* pib = &g_parti[(size_t)b*4608 + (size_t)half*64*36];
  for (int i = 0; i < 64; i++) {
    const float* pi = pib + i*36;
    float4* od = (float4*)(outb + (size_t)i*4608);
    int a0 = (tid*4) % 36;
    for (int f = tid; f < 1152; f += 256) {
      float4 v = pjb4[f];
      int aa = a0;
      v.x += __ldg(&pi[aa]); aa = (aa==35)?0:aa+1;
      v.y += __ldg(&pi[aa]); aa = (aa==35)?0:aa+1;
      v.z += __ldg(&pi[aa]); aa = (aa==35)?0:aa+1;
      v.w += __ldg(&pi[aa]);
      od[f] = v;
      a0 += 16;
      if (a0 >= 36) a0 -= 36;
    }
  }
}

extern "C" void kernel_launch(void* const* d_in, const int* in_sizes, int n_in,
                              void* d_out, int out_size) {
  const float* emb  = (const float*)d_in[0];
  const float* Wihf = (const float*)d_in[1];
  const float* Whhf = (const float*)d_in[2];
  const float* bihf = (const float*)d_in[3];
  const float* bhhf = (const float*)d_in[4];
  const float* Wihb = (const float*)d_in[5];
  const float* Whhb = (const float*)d_in[6];
  const float* bihb = (const float*)d_in[7];
  const float* bhhb = (const float*)d_in[8];
  const float* Wev  = (const float*)d_in[9];
  const float* bev  = (const float*)d_in[10];
  const float* Warg = (const float*)d_in[11];
  const float* barg = (const float*)d_in[12];
  const int*   ids  = (const int*)d_in[13];
  float* out = (float*)d_out;

  cudaFuncSetAttribute(k_lstm, cudaFuncAttributeMaxDynamicSharedMemorySize, 159744);

  k_init_a<<<1, 32>>>();                                            // 1
  dim3 gp(128, 16);
  k_pre<<<gp, 256>>>(emb, Wihf, Wihb, bihf, bhhf, bihb, bhhb, ids); // 2
  k_init_b<<<256, 256>>>();                                         // 3
  k_lstm<<<128, 256, 159744>>>(Whhf, Whhb);                         // 4 (profiled slot)
  k_evcomb<<<128, 256>>>(Wev, bev, Warg, out);                      // 5
  k_evscan<<<64, 32>>>(Wev, out);                                   // 6
  k_add<<<128, 256>>>(barg, out + 278528);                          // 7
}

// round 17
// speedup vs baseline: 1.1604x; 1.0579x over previous
#include <cuda_runtime.h>
#include <cuda_bf16.h>
#include <math.h>

#define FMA2(d,a,b) asm("fma.rn.f32x2 %0, %1, %2, %0;" : "+l"(d) : "l"(a), "l"(b))
#define DUP2(d,s)   asm("mov.b64 %0, {%1,%1};" : "=l"(d) : "f"(s))
#define PACK2(d,lo,hi) asm("mov.b64 %0, {%1,%2};" : "=l"(d) : "f"(lo), "f"(hi))

__device__ __forceinline__ float2 u2f(unsigned long long v) {
  float2 r; asm("mov.b64 {%0,%1}, %2;" : "=f"(r.x), "=f"(r.y) : "l"(v)); return r;
}

// ---------------- device scratch ----------------
__device__ float g_WT[2][300][1024];          // [dir][k][gate_row] transposed W_ih
__device__ float g_pre2[2][256][128][64][4];  // [dir][j][t][b][gate] 64MB
__device__ float g_hbuf[2][2][8][256][8];     // [parity][dir][bslice][j][bloc]
__device__ float g_hall[128][512][64];        // [t][c][b]
__device__ float g_parti[64*128*36];
__device__ float g_partj[64*128*36];
__device__ unsigned int g_cnt[16];            // [dir*8 + bslice]

__global__ void k_init_a() {
  if (threadIdx.x < 16) g_cnt[threadIdx.x] = 0u;
}
__global__ void k_init_b() {
  int i = blockIdx.x*blockDim.x + threadIdx.x;   // 65536 threads
  (&g_hbuf[0][0][0][0][0])[i] = 0.f;
}

// ============ 0) W transpose (R15-proven): g_WT[dir][k][row] = Wih[row][k] ============
__global__ void __launch_bounds__(256) k_trW(const float* __restrict__ Wf,
                                             const float* __restrict__ Wb)
{
  __shared__ float tile[64*61];
  int dir = blockIdx.z;
  int r0 = blockIdx.x*64;     // 16 blocks
  int k0 = blockIdx.y*60;     // 5 blocks
  const float* W = dir ? Wb : Wf;
  int tid = threadIdx.x;
  for (int e = tid; e < 3840; e += 256) {
    int r = e / 60, kk = e % 60;
    tile[r*61 + kk] = W[(size_t)(r0 + r)*300 + k0 + kk];
  }
  __syncthreads();
  for (int e = tid; e < 3840; e += 256) {
    int kk = e >> 6, r = e & 63;
    g_WT[dir][k0 + kk][r0 + r] = tile[r*61 + kk];
  }
}

// ============ 1) input GEMM (R13 structure; W staged from transposed g_WT) ============
__global__ void __launch_bounds__(256) k_pre(
    const float* __restrict__ emb,
    const float* __restrict__ bihf, const float* __restrict__ bhhf,
    const float* __restrict__ bihb, const float* __restrict__ bhhb,
    const int* __restrict__ ids)
{
  __shared__ __align__(16) float  A_s[20][64];
  __shared__ __align__(16) float2 W2p[20*128];
  __shared__ int id_s[64];
  int tid = threadIdx.x;
  int t  = blockIdx.x;
  int rt = blockIdx.y;
  int dir = rt >> 3, jt = rt & 7;
  if (tid < 64) id_s[tid] = ids[tid*128 + t];   // b = tid
  __syncthreads();

  int tokq = tid & 7, rowq = tid >> 3;          // rowq = j_local (0..31)
  int tok0 = tokq*8;
  int j = jt*32 + rowq;
  unsigned long long acc[4][4];                 // [gate][token-pair]
  #pragma unroll
  for (int i=0;i<4;i++){ acc[i][0]=0ull; acc[i][1]=0ull; acc[i][2]=0ull; acc[i][3]=0ull; }

  for (int kc = 0; kc < 15; kc++) {
    int k0 = kc*20;
    __syncthreads();
    for (int e = tid; e < 320; e += 256) {
      int d4 = e % 5, tok = e / 5;
      float4 v = *(const float4*)(emb + (size_t)id_s[tok]*300 + k0 + d4*4);
      A_s[d4*4+0][tok] = v.x; A_s[d4*4+1][tok] = v.y;
      A_s[d4*4+2][tok] = v.z; A_s[d4*4+3][tok] = v.w;
    }
    // staging from transposed W: per warp, 4 contiguous 32-float blocks (4 sectors)
    for (int e = tid; e < 2560; e += 256) {
      int k = e >> 7, r = e & 127;              // r = jl*4 + gate
      int gate = r & 3, jl = r >> 2;
      float w = g_WT[dir][k0 + k][gate*256 + jt*32 + jl];
      W2p[k*128 + r] = make_float2(w, w);
    }
    __syncthreads();
    #pragma unroll
    for (int k = 0; k < 20; k++) {
      ulonglong2 a0 = *(const ulonglong2*)&A_s[k][tok0];
      ulonglong2 a1 = *(const ulonglong2*)&A_s[k][tok0+4];
      ulonglong2 wA = *(const ulonglong2*)&W2p[k*128 + rowq*4];
      ulonglong2 wB = *(const ulonglong2*)&W2p[k*128 + rowq*4 + 2];
      FMA2(acc[0][0], wA.x, a0.x); FMA2(acc[0][1], wA.x, a0.y);
      FMA2(acc[0][2], wA.x, a1.x); FMA2(acc[0][3], wA.x, a1.y);
      FMA2(acc[1][0], wA.y, a0.x); FMA2(acc[1][1], wA.y, a0.y);
      FMA2(acc[1][2], wA.y, a1.x); FMA2(acc[1][3], wA.y, a1.y);
      FMA2(acc[2][0], wB.x, a0.x); FMA2(acc[2][1], wB.x, a0.y);
      FMA2(acc[2][2], wB.x, a1.x); FMA2(acc[2][3], wB.x, a1.y);
      FMA2(acc[3][0], wB.y, a0.x); FMA2(acc[3][1], wB.y, a0.y);
      FMA2(acc[3][2], wB.y, a1.x); FMA2(acc[3][3], wB.y, a1.y);
    }
  }
  float2 eg[4][4];
  float bias[4];
  #pragma unroll
  for (int g = 0; g < 4; g++) {
    int grow = g*256 + j;
    bias[g] = dir ? (bihb[grow] + bhhb[grow]) : (bihf[grow] + bhhf[grow]);
    #pragma unroll
    for (int q = 0; q < 4; q++) eg[g][q] = u2f(acc[g][q]);
  }
  float* outp = &g_pre2[dir][j][t][tok0][0];
  #pragma unroll
  for (int tt = 0; tt < 8; tt++) {
    int q = tt >> 1;
    float4 o;
    o.x = ((tt&1) ? eg[0][q].y : eg[0][q].x) + bias[0];
    o.y = ((tt&1) ? eg[1][q].y : eg[1][q].x) + bias[1];
    o.z = ((tt&1) ? eg[2][q].y : eg[2][q].x) + bias[2];
    o.w = ((tt&1) ? eg[3][q].y : eg[3][q].x) + bias[3];
    *(float4*)(outp + tt*4) = o;
  }
}

// ============ 2) persistent BiLSTM (R13/R16 verbatim — best measured: 518-521us) ======
__global__ void __launch_bounds__(256,1) k_lstm(const float* __restrict__ Whhf,
                                                const float* __restrict__ Whhb)
{
  extern __shared__ float sm[];
  float* W_s    = sm;            // [k*132 + r], 33792 floats
  float* h_s    = sm + 33792;    // [k][bloc] 256x8, 2048 floats
  float* part_s = sm + 35840;    // [kc*1024 + r*8 + bl], 4096 floats

  int tid = threadIdx.x, cta = blockIdx.x;
  int dir = cta >> 6, rem = cta & 63;
  int bslice = rem >> 3, rslice = rem & 7;
  const float* Whh = dir ? Whhb : Whhf;

  for (int e = tid; e < 32768; e += 256) {
    int r = e >> 8, k = e & 255;
    int grow = (r >> 5)*256 + rslice*32 + (r & 31);
    W_s[k*132 + r] = Whh[(size_t)grow*256 + k];
  }
  __syncthreads();

  int w8 = tid >> 5, lane = tid & 31;
  int kc = w8 & 3, rw = w8 >> 2;
  int rbase = rw*64 + (lane >> 1)*4;
  int bbase = (lane & 1)*4;
  int kstart = kc*64;
  int jloc = tid >> 3, bloc = tid & 7;
  int j = rslice*32 + jloc;
  int gb = bslice*8 + bloc;
  const float4* pgp = (const float4*)&g_pre2[dir][j][0][0][0];
  unsigned cidx = (unsigned)(dir*8 + bslice);
  unsigned hs_u32 = (unsigned)__cvta_generic_to_shared(h_s);
  float c = 0.f;

  for (int sidx = 0; sidx < 128; sidx++) {
    int t = dir ? (127 - sidx) : sidx;
    float4 pg = __ldg(&pgp[t*64 + gb]);

    if (sidx > 0) {
      if (tid == 0) {
        unsigned tgt = (unsigned)(sidx*8);
        while (*((volatile unsigned int*)&g_cnt[cidx]) < tgt) { }
        __threadfence();
      }
      __syncthreads();
    }
    {
      const float4* src = (const float4*)&g_hbuf[sidx & 1][dir][bslice][0][0];
      asm volatile("cp.async.cg.shared.global [%0], [%1], 16;"
                   :: "r"(hs_u32 + tid*16), "l"(src + tid));
      asm volatile("cp.async.cg.shared.global [%0], [%1], 16;"
                   :: "r"(hs_u32 + (tid+256)*16), "l"(src + tid + 256));
      asm volatile("cp.async.commit_group;");
      asm volatile("cp.async.wait_group 0;" ::: "memory");
    }
    __syncthreads();

    unsigned long long a00=0,a01=0,a10=0,a11=0,a20=0,a21=0,a30=0,a31=0;
    #pragma unroll 4
    for (int kk = 0; kk < 64; kk++) {
      int k = kstart + kk;
      float4 wv = *(const float4*)&W_s[k*132 + rbase];
      ulonglong2 hv = *(const ulonglong2*)&h_s[k*8 + bbase];
      unsigned long long w0d,w1d,w2d,w3d;
      DUP2(w0d, wv.x); DUP2(w1d, wv.y); DUP2(w2d, wv.z); DUP2(w3d, wv.w);
      FMA2(a00, w0d, hv.x); FMA2(a01, w0d, hv.y);
      FMA2(a10, w1d, hv.x); FMA2(a11, w1d, hv.y);
      FMA2(a20, w2d, hv.x); FMA2(a21, w2d, hv.y);
      FMA2(a30, w3d, hv.x); FMA2(a31, w3d, hv.y);
    }
    {
      ulonglong2 v;
      v.x = a00; v.y = a01; *(ulonglong2*)&part_s[kc*1024 + (rbase+0)*8 + bbase] = v;
      v.x = a10; v.y = a11; *(ulonglong2*)&part_s[kc*1024 + (rbase+1)*8 + bbase] = v;
      v.x = a20; v.y = a21; *(ulonglong2*)&part_s[kc*1024 + (rbase+2)*8 + bbase] = v;
      v.x = a30; v.y = a31; *(ulonglong2*)&part_s[kc*1024 + (rbase+3)*8 + bbase] = v;
    }
    __syncthreads();

    int ri = jloc, rf = 32 + jloc, rg = 64 + jloc, ro = 96 + jloc;
    float iv = pg.x + part_s[ri*8+bloc] + part_s[1024 + ri*8+bloc]
                    + part_s[2048 + ri*8+bloc] + part_s[3072 + ri*8+bloc];
    float fv = pg.y + part_s[rf*8+bloc] + part_s[1024 + rf*8+bloc]
                    + part_s[2048 + rf*8+bloc] + part_s[3072 + rf*8+bloc];
    float gv = pg.z + part_s[rg*8+bloc] + part_s[1024 + rg*8+bloc]
                    + part_s[2048 + rg*8+bloc] + part_s[3072 + rg*8+bloc];
    float ov = pg.w + part_s[ro*8+bloc] + part_s[1024 + ro*8+bloc]
                    + part_s[2048 + ro*8+bloc] + part_s[3072 + ro*8+bloc];
    iv = 1.f/(1.f+__expf(-iv));
    fv = 1.f/(1.f+__expf(-fv));
    gv = tanhf(gv);
    ov = 1.f/(1.f+__expf(-ov));
    c = fv*c + iv*gv;
    float h = ov*tanhf(c);
    g_hbuf[(sidx+1)&1][dir][bslice][j][bloc] = h;
    g_hall[t][dir*256 + j][gb] = h;
    __syncthreads();
    if (tid == 0) { __threadfence(); atomicAdd(&g_cnt[cidx], 1u); }
  }
}

// ============ 3a) combined GEMM, conflict-free h layout [k][b] (R15/R16, passed) ======
__global__ void __launch_bounds__(256) k_evcomb(const float* __restrict__ Wev,
                                                const float* __restrict__ bev,
                                                const float* __restrict__ Warg,
                                                float* __restrict__ out0)
{
  __shared__ __align__(16) float W_s[106*64];
  __shared__ __align__(16) float h_s[64*64];
  int t = blockIdx.x;
  int tid = threadIdx.x;
  int b = tid & 63;
  int g = tid >> 6;
  unsigned long long acc2[27];
  #pragma unroll
  for (int i=0;i<27;i++) acc2[i] = 0ull;

  for (int c0 = 0; c0 < 512; c0 += 64) {
    __syncthreads();
    for (int e = tid; e < 106*64; e += 256) {
      int r = e >> 6, kk = e & 63;
      float w;
      if (r < 34)       w = Wev[(size_t)r*545 + c0 + kk];
      else if (r < 70)  w = Warg[(size_t)(r-34)*1024 + c0 + kk];
      else              w = Warg[(size_t)(r-70)*1024 + 512 + c0 + kk];
      W_s[e] = w;
    }
    for (int e = tid; e < 4096; e += 256) {
      int kk = e >> 6, bb = e & 63;
      h_s[kk*64 + bb] = g_hall[t][c0+kk][bb];
    }
    __syncthreads();
    #pragma unroll 4
    for (int k = 0; k < 64; k += 4) {
      float h0 = h_s[(k+0)*64 + b];
      float h1 = h_s[(k+1)*64 + b];
      float h2 = h_s[(k+2)*64 + b];
      float h3 = h_s[(k+3)*64 + b];
      unsigned long long hx, hy;
      PACK2(hx, h0, h1); PACK2(hy, h2, h3);
      #pragma unroll
      for (int ii = 0; ii < 27; ii++) {
        int r = g + ii*4;
        if (r < 106) {
          ulonglong2 wv = *(const ulonglong2*)&W_s[r*64 + k];
          FMA2(acc2[ii], wv.x, hx);
          FMA2(acc2[ii], wv.y, hy);
        }
      }
    }
  }
  #pragma unroll
  for (int ii = 0; ii < 27; ii++) {
    int r = g + ii*4;
    if (r < 106) {
      float2 f = u2f(acc2[ii]);
      float v = f.x + f.y;
      if (r < 34)
        out0[((size_t)b*128 + t)*34 + r] = v + bev[r];
      else if (r < 70)
        g_partj[((size_t)b*128 + t)*36 + (r-34)] = v;
      else
        g_parti[((size_t)b*128 + t)*36 + (r-70)] = v;
    }
  }
}

// ============ 3b) event scan: SMEM-resident (R15/R16, passed) ============
__global__ void __launch_bounds__(32) k_evscan(const float* __restrict__ Wev,
                                               float* __restrict__ out0)
{
  __shared__ float base[128*34];
  int b = blockIdx.x;
  int lane = threadIdx.x;
  float* basep = out0 + (size_t)b*128*34;
  for (int e = lane; e < 4352; e += 32) base[e] = basep[e];
  __syncwarp();

  float add0 = 0.f, add1 = 0.f;
  unsigned long long gmask = 0ull;
  for (int t = 0; t < 128; t++) {
    float v0 = base[t*34 + lane] + add0;
    float v1 = (lane < 2) ? (base[t*34 + 32 + lane] + add1) : -INFINITY;
    base[t*34 + lane] = v0;
    if (lane < 2) base[t*34 + 32 + lane] = v1;

    float mv = v0; int mi = lane;
    if (lane < 2 && v1 > mv) { mv = v1; mi = lane + 32; }
    #pragma unroll
    for (int o = 16; o > 0; o >>= 1) {
      float ov = __shfl_xor_sync(0xffffffffu, mv, o);
      int   oi = __shfl_xor_sync(0xffffffffu, mi, o);
      if (ov > mv || (ov == mv && oi < mi)) { mv = ov; mi = oi; }
    }
    if (mi > 0) {
      unsigned long long bit = 1ull << (mi - 1);
      if (!(gmask & bit)) {
        gmask |= bit;
        add0 += Wev[(size_t)lane*545 + 512 + (mi-1)];
        if (lane < 2) add1 += Wev[(size_t)(lane+32)*545 + 512 + (mi-1)];
      }
    }
  }
  __syncwarp();
  for (int e = lane; e < 4352; e += 32) basep[e] = base[e];
}

// ============ 5) broadcast add (R13/R16 verbatim) ============
__global__ void __launch_bounds__(256) k_add(const float* __restrict__ barg,
                                             float* __restrict__ out1)
{
  __shared__ __align__(16) float pjb[128*36];
  int b = blockIdx.x >> 1, half = blockIdx.x & 1;
  int tid = threadIdx.x;
  for (int e = tid; e < 4608; e += 256)
    pjb[e] = g_partj[(size_t)b*4608 + e] + barg[e % 36];
  __syncthreads();
  const float4* pjb4 = (const float4*)pjb;
  float* outb = out1 + (size_t)b*589824 + (size_t)half*294912;
  const float* pib = &g_parti[(size_t)b*4608 + (size_t)half*64*36];
  for (int i = 0; i < 64; i++) {
    const float* pi = pib + i*36;
    float4* od = (float4*)(outb + (size_t)i*4608);
    int a0 = (tid*4) % 36;
    for (int f = tid; f < 1152; f += 256) {
      float4 v = pjb4[f];
      int aa = a0;
      v.x += __ldg(&pi[aa]); aa = (aa==35)?0:aa+1;
      v.y += __ldg(&pi[aa]); aa = (aa==35)?0:aa+1;
      v.z += __ldg(&pi[aa]); aa = (aa==35)?0:aa+1;
      v.w += __ldg(&pi[aa]);
      od[f] = v;
      a0 += 16;
      if (a0 >= 36) a0 -= 36;
    }
  }
}

extern "C" void kernel_launch(void* const* d_in, const int* in_sizes, int n_in,
                              void* d_out, int out_size) {
  const float* emb  = (const float*)d_in[0];
  const float* Wihf = (const float*)d_in[1];
  const float* Whhf = (const float*)d_in[2];
  const float* bihf = (const float*)d_in[3];
  const float* bhhf = (const float*)d_in[4];
  const float* Wihb = (const float*)d_in[5];
  const float* Whhb = (const float*)d_in[6];
  const float* bihb = (const float*)d_in[7];
  const float* bhhb = (const float*)d_in[8];
  const float* Wev  = (const float*)d_in[9];
  const float* bev  = (const float*)d_in[10];
  const float* Warg = (const float*)d_in[11];
  const float* barg = (const float*)d_in[12];
  const int*   ids  = (const int*)d_in[13];
  float* out = (float*)d_out;

  cudaFuncSetAttribute(k_lstm, cudaFuncAttributeMaxDynamicSharedMemorySize, 159744);

  k_init_a<<<1, 32>>>();                                            // 1
  dim3 gt(16, 5, 2);
  k_trW<<<gt, 256>>>(Wihf, Wihb);                                   // 2
  k_init_b<<<256, 256>>>();                                         // 3
  dim3 gp(128, 16);
  k_pre<<<gp, 256>>>(emb, bihf, bhhf, bihb, bhhb, ids);             // 4 (profiled slot)
  k_lstm<<<128, 256, 159744>>>(Whhf, Whhb);                         // 5
  k_evcomb<<<128, 256>>>(Wev, bev, Warg, out);                      // 6
  k_evscan<<<64, 32>>>(Wev, out);                                   // 7
  k_add<<<128, 256>>>(barg, out + 278528);                          // 8
}